// round 6
// baseline (speedup 1.0000x reference)
#include <cuda_runtime.h>
#include <math_constants.h>

// MC3DAD curvature: per-point kNN (k=5) covariance trace, batch-normalized.
// pcd: [8, 4096, 3] fp32.  out: [8, 4096] fp32.

#define NPTS    4096
#define QPB     256         // queries per block
#define THREADS 512         // 2 threads per query (candidate-split)
#define KNN     5

// Sorted-ascending 5-element insert; strict '<' everywhere preserves
// jax top_k's stable lowest-index tie-break (equal value -> earlier index wins).
// Clamp to 0 to replicate sqrt(max(d2,0)) ordering semantics.
__device__ __forceinline__ void try_insert(float v, int j,
    float& bd0, float& bd1, float& bd2, float& bd3, float& bd4,
    int& bi0, int& bi1, int& bi2, int& bi3, int& bi4)
{
    v = fmaxf(v, 0.0f);
    if (v < bd4) {
        bd4 = v; bi4 = j;
        if (bd4 < bd3) { float t=bd4; bd4=bd3; bd3=t; int ti=bi4; bi4=bi3; bi3=ti;
          if (bd3 < bd2) { t=bd3; bd3=bd2; bd2=t; ti=bi3; bi3=bi2; bi2=ti;
            if (bd2 < bd1) { t=bd2; bd2=bd1; bd1=t; ti=bi2; bi2=bi1; bi1=ti;
              if (bd1 < bd0) { t=bd1; bd1=bd0; bd0=t; ti=bi1; bi1=bi0; bi0=ti; }
            }
          }
        }
    }
}

__global__ __launch_bounds__(THREADS)
void knn_curv_kernel(const float* __restrict__ pcd, float* __restrict__ out)
{
    extern __shared__ float smem[];
    float* xs = smem;                 // [4096]
    float* ys = smem + NPTS;          // [4096]
    float* zs = smem + 2 * NPTS;      // [4096]
    float* sq = smem + 3 * NPTS;      // [4096]
    float* md = smem + 4 * NPTS;      // [THREADS*KNN] merge dists
    int*   mi = (int*)(md + THREADS * KNN); // [THREADS*KNN] merge idx

    const int b   = blockIdx.y;
    const int tid = threadIdx.x;
    const float* g = pcd + (size_t)b * NPTS * 3;

    // Stage batch point cloud into SMEM as SoA (coalesced gmem reads).
    for (int i = tid; i < NPTS * 3; i += THREADS) {
        float v = g[i];
        int p = i / 3, c = i - 3 * p;
        float* dst = (c == 0) ? xs : (c == 1) ? ys : zs;
        dst[p] = v;
    }
    __syncthreads();
    for (int p = tid; p < NPTS; p += THREADS) {
        float x = xs[p], y = ys[p], z = zs[p];
        sq[p] = fmaf(x, x, fmaf(y, y, z * z));
    }
    __syncthreads();

    const int lane = tid & (QPB - 1);
    const int half = tid >> 8;                  // 0 or 1: candidate-range split
    const int qi   = blockIdx.x * QPB + lane;   // query index within batch
    const float qx = xs[qi], qy = ys[qi], qz = zs[qi];
    const float sqq = sq[qi];

    float bd0 = CUDART_INF_F, bd1 = CUDART_INF_F, bd2 = CUDART_INF_F,
          bd3 = CUDART_INF_F, bd4 = CUDART_INF_F;
    int bi0 = 0, bi1 = 0, bi2 = 0, bi3 = 0, bi4 = 0;

    const int j0 = half * (NPTS / 2);
    #pragma unroll 2
    for (int j = j0; j < j0 + NPTS / 2; j += 4) {
        float4 X = *(const float4*)(xs + j);
        float4 Y = *(const float4*)(ys + j);
        float4 Z = *(const float4*)(zs + j);
        float4 S = *(const float4*)(sq + j);
        float t0 = fmaf(qx, X.x, fmaf(qy, Y.x, qz * Z.x));
        float t1 = fmaf(qx, X.y, fmaf(qy, Y.y, qz * Z.y));
        float t2 = fmaf(qx, X.z, fmaf(qy, Y.z, qz * Z.z));
        float t3 = fmaf(qx, X.w, fmaf(qy, Y.w, qz * Z.w));
        float d0 = fmaf(-2.0f, t0, S.x + sqq);
        float d1 = fmaf(-2.0f, t1, S.y + sqq);
        float d2 = fmaf(-2.0f, t2, S.z + sqq);
        float d3 = fmaf(-2.0f, t3, S.w + sqq);
        float m = fminf(fminf(d0, d1), fminf(d2, d3));
        if (m < bd4) {   // rare (~1%) path: actually update the top-5
            try_insert(d0, j + 0, bd0, bd1, bd2, bd3, bd4, bi0, bi1, bi2, bi3, bi4);
            try_insert(d1, j + 1, bd0, bd1, bd2, bd3, bd4, bi0, bi1, bi2, bi3, bi4);
            try_insert(d2, j + 2, bd0, bd1, bd2, bd3, bd4, bi0, bi1, bi2, bi3, bi4);
            try_insert(d3, j + 3, bd0, bd1, bd2, bd3, bd4, bi0, bi1, bi2, bi3, bi4);
        }
    }

    // Publish both halves' top-5 lists for the merge.
    {
        int base = tid * KNN;
        md[base + 0] = bd0; mi[base + 0] = bi0;
        md[base + 1] = bd1; mi[base + 1] = bi1;
        md[base + 2] = bd2; mi[base + 2] = bi2;
        md[base + 3] = bd3; mi[base + 3] = bi3;
        md[base + 4] = bd4; mi[base + 4] = bi4;
    }
    __syncthreads();

    if (tid < QPB) {
        // Merge list A (half 0, lower indices) with list B (half 1).
        // On ties take A (lower global index) -> matches top_k stability.
        const int a = tid * KNN;
        const int bb = (tid + QPB) * KNN;
        int ai = 0, bj = 0;
        int sel[KNN];
        #pragma unroll
        for (int s = 0; s < KNN; s++) {
            float da = md[a + ai];
            float db = md[bb + bj];
            if (da <= db) { sel[s] = mi[a + ai]; ai++; }
            else          { sel[s] = mi[bb + bj]; bj++; }
        }

        // Gather neighbors, centroid, covariance trace.
        float nx[KNN], ny[KNN], nz[KNN];
        float cx = 0.0f, cy = 0.0f, cz = 0.0f;
        #pragma unroll
        for (int s = 0; s < KNN; s++) {
            nx[s] = xs[sel[s]]; ny[s] = ys[sel[s]]; nz[s] = zs[sel[s]];
            cx += nx[s]; cy += ny[s]; cz += nz[s];
        }
        cx *= (1.0f / KNN); cy *= (1.0f / KNN); cz *= (1.0f / KNN);
        float ss = 0.0f;
        #pragma unroll
        for (int s = 0; s < KNN; s++) {
            float dx = nx[s] - cx, dy = ny[s] - cy, dz = nz[s] - cz;
            ss = fmaf(dx, dx, ss);
            ss = fmaf(dy, dy, ss);
            ss = fmaf(dz, dz, ss);
        }
        out[b * NPTS + qi] = ss * (1.0f / (KNN - 1));
    }
}

// Per-batch normalization: out[b,n] = trace[b,n] / (sum_n trace[b,n] + 1e-8)
__global__ __launch_bounds__(512)
void norm_kernel(float* __restrict__ out)
{
    __shared__ float red[512];
    const int b = blockIdx.x;
    const int tid = threadIdx.x;
    float* o = out + b * NPTS;

    float v[8];
    float s = 0.0f;
    #pragma unroll
    for (int r = 0; r < 8; r++) { v[r] = o[tid + r * 512]; s += v[r]; }
    red[tid] = s;
    __syncthreads();
    #pragma unroll
    for (int off = 256; off > 0; off >>= 1) {
        if (tid < off) red[tid] += red[tid + off];
        __syncthreads();
    }
    float inv = 1.0f / (red[0] + 1e-8f);
    #pragma unroll
    for (int r = 0; r < 8; r++) o[tid + r * 512] = v[r] * inv;
}

extern "C" void kernel_launch(void* const* d_in, const int* in_sizes, int n_in,
                              void* d_out, int out_size)
{
    const float* pcd = (const float*)d_in[0];   // [8, 4096, 3] fp32
    float* out = (float*)d_out;                 // [8, 4096] fp32
    (void)in_sizes; (void)n_in; (void)out_size; // k is fixed at 5

    const size_t smem_bytes = (size_t)4 * NPTS * sizeof(float)        // xs,ys,zs,sq
                            + (size_t)THREADS * KNN * sizeof(float)   // md
                            + (size_t)THREADS * KNN * sizeof(int);    // mi
    cudaFuncSetAttribute(knn_curv_kernel,
                         cudaFuncAttributeMaxDynamicSharedMemorySize,
                         (int)smem_bytes);

    dim3 grid(NPTS / QPB, 8);   // (16, 8) = 128 blocks: one wave
    knn_curv_kernel<<<grid, THREADS, smem_bytes>>>(pcd, out);
    norm_kernel<<<8, 512>>>(out);
}

// round 9
// speedup vs baseline: 1.0332x; 1.0332x over previous
#include <cuda_runtime.h>
#include <math_constants.h>

// MC3DAD curvature: per-point kNN (k=5) covariance trace, batch-normalized.
// pcd: [8, 4096, 3] fp32.  out: [8, 4096] fp32.

#define NPTS 4096
#define QPB  256     // one thread per query
#define KNN  5

typedef unsigned long long ull;

// ---- packed f32x2 helpers (Blackwell sm_100+) ----
__device__ __forceinline__ ull pack2(float lo, float hi) {
    ull r; asm("mov.b64 %0, {%1, %2};" : "=l"(r) : "f"(lo), "f"(hi)); return r;
}
__device__ __forceinline__ ull mul2(ull a, ull b) {
    ull d; asm("mul.rn.f32x2 %0, %1, %2;" : "=l"(d) : "l"(a), "l"(b)); return d;
}
__device__ __forceinline__ ull fma2(ull a, ull b, ull c) {
    ull d; asm("fma.rn.f32x2 %0, %1, %2, %3;" : "=l"(d) : "l"(a), "l"(b), "l"(c)); return d;
}
// fused fma + unpack to two scalar floats (register-pair aliasing, no real movs)
__device__ __forceinline__ void fma2u(float& lo, float& hi, ull a, ull b, ull c) {
    asm("{\n\t.reg .b64 t;\n\tfma.rn.f32x2 t, %2, %3, %4;\n\tmov.b64 {%0, %1}, t;\n\t}"
        : "=f"(lo), "=f"(hi) : "l"(a), "l"(b), "l"(c));
}

// Branchless sorted-ascending top-5 insert. Strict '<' preserves jax top_k's
// stable lowest-index tie-break (scan order is ascending j).
// Values live in the shifted domain d2 - sqq; clamp is max(v, -sqq).
__device__ __forceinline__ void ins5(float v, int j, float msqq,
    float& bd0, float& bd1, float& bd2, float& bd3, float& bd4,
    int& bi0, int& bi1, int& bi2, int& bi3, int& bi4)
{
    v = fmaxf(v, msqq);
    if (v < bd4) {
        bool p3 = v < bd3;
        bool p2 = v < bd2;
        bool p1 = v < bd1;
        bool p0 = v < bd0;
        bd4 = p3 ? bd3 : v;               bi4 = p3 ? bi3 : j;
        bd3 = p3 ? (p2 ? bd2 : v) : bd3;  bi3 = p3 ? (p2 ? bi2 : j) : bi3;
        bd2 = p2 ? (p1 ? bd1 : v) : bd2;  bi2 = p2 ? (p1 ? bi1 : j) : bi2;
        bd1 = p1 ? (p0 ? bd0 : v) : bd1;  bi1 = p1 ? (p0 ? bi0 : j) : bi1;
        bd0 = p0 ? v : bd0;               bi0 = p0 ? j : bi0;
    }
}

__global__ __launch_bounds__(QPB)
void knn_curv_kernel(const float* __restrict__ pcd, float* __restrict__ out)
{
    extern __shared__ float smem[];
    float* xs = smem;                 // [4096]
    float* ys = smem + NPTS;          // [4096]
    float* zs = smem + 2 * NPTS;      // [4096]
    float* sq = smem + 3 * NPTS;      // [4096]

    const int b   = blockIdx.y;
    const int tid = threadIdx.x;
    const float* g = pcd + (size_t)b * NPTS * 3;

    // Stage batch point cloud into SMEM as SoA.
    for (int i = tid; i < NPTS * 3; i += QPB) {
        float v = g[i];
        int p = i / 3, c = i - 3 * p;
        float* dst = (c == 0) ? xs : (c == 1) ? ys : zs;
        dst[p] = v;
    }
    __syncthreads();
    for (int p = tid; p < NPTS; p += QPB) {
        float x = xs[p], y = ys[p], z = zs[p];
        sq[p] = fmaf(x, x, fmaf(y, y, z * z));
    }
    __syncthreads();

    const int qi = blockIdx.x * QPB + tid;   // query index within batch
    const float qx = xs[qi], qy = ys[qi], qz = zs[qi];
    const float sqq = sq[qi];
    const float msqq = -sqq;

    const ull qx2 = pack2(qx, qx);
    const ull qy2 = pack2(qy, qy);
    const ull qz2 = pack2(qz, qz);
    const ull n2  = pack2(-2.0f, -2.0f);

    float bd0 = CUDART_INF_F, bd1 = CUDART_INF_F, bd2 = CUDART_INF_F,
          bd3 = CUDART_INF_F, bd4 = CUDART_INF_F;
    int bi0 = 0, bi1 = 0, bi2 = 0, bi3 = 0, bi4 = 0;

    for (int j = 0; j < NPTS; j += 8) {
        // 8 candidates as 4 packed pairs per coordinate array.
        longlong2 X0 = *(const longlong2*)(xs + j);
        longlong2 X1 = *(const longlong2*)(xs + j + 4);
        longlong2 Y0 = *(const longlong2*)(ys + j);
        longlong2 Y1 = *(const longlong2*)(ys + j + 4);
        longlong2 Z0 = *(const longlong2*)(zs + j);
        longlong2 Z1 = *(const longlong2*)(zs + j + 4);
        longlong2 S0 = *(const longlong2*)(sq + j);
        longlong2 S1 = *(const longlong2*)(sq + j + 4);

        float v0, v1, v2, v3, v4, v5, v6, v7;
        { ull t = mul2(qz2, (ull)Z0.x); t = fma2(qy2, (ull)Y0.x, t);
          t = fma2(qx2, (ull)X0.x, t);  fma2u(v0, v1, n2, t, (ull)S0.x); }
        { ull t = mul2(qz2, (ull)Z0.y); t = fma2(qy2, (ull)Y0.y, t);
          t = fma2(qx2, (ull)X0.y, t);  fma2u(v2, v3, n2, t, (ull)S0.y); }
        { ull t = mul2(qz2, (ull)Z1.x); t = fma2(qy2, (ull)Y1.x, t);
          t = fma2(qx2, (ull)X1.x, t);  fma2u(v4, v5, n2, t, (ull)S1.x); }
        { ull t = mul2(qz2, (ull)Z1.y); t = fma2(qy2, (ull)Y1.y, t);
          t = fma2(qx2, (ull)X1.y, t);  fma2u(v6, v7, n2, t, (ull)S1.y); }

        float m = fminf(fminf(fminf(v0, v1), fminf(v2, v3)),
                        fminf(fminf(v4, v5), fminf(v6, v7)));
        if (m < bd4) {   // warp-level rare path
            ins5(v0, j + 0, msqq, bd0, bd1, bd2, bd3, bd4, bi0, bi1, bi2, bi3, bi4);
            ins5(v1, j + 1, msqq, bd0, bd1, bd2, bd3, bd4, bi0, bi1, bi2, bi3, bi4);
            ins5(v2, j + 2, msqq, bd0, bd1, bd2, bd3, bd4, bi0, bi1, bi2, bi3, bi4);
            ins5(v3, j + 3, msqq, bd0, bd1, bd2, bd3, bd4, bi0, bi1, bi2, bi3, bi4);
            ins5(v4, j + 4, msqq, bd0, bd1, bd2, bd3, bd4, bi0, bi1, bi2, bi3, bi4);
            ins5(v5, j + 5, msqq, bd0, bd1, bd2, bd3, bd4, bi0, bi1, bi2, bi3, bi4);
            ins5(v6, j + 6, msqq, bd0, bd1, bd2, bd3, bd4, bi0, bi1, bi2, bi3, bi4);
            ins5(v7, j + 7, msqq, bd0, bd1, bd2, bd3, bd4, bi0, bi1, bi2, bi3, bi4);
        }
    }

    // Gather neighbors, centroid, covariance trace (k=5, unbiased /(k-1)).
    float nx[KNN], ny[KNN], nz[KNN];
    int sel[KNN] = { bi0, bi1, bi2, bi3, bi4 };
    float cx = 0.0f, cy = 0.0f, cz = 0.0f;
    #pragma unroll
    for (int s = 0; s < KNN; s++) {
        nx[s] = xs[sel[s]]; ny[s] = ys[sel[s]]; nz[s] = zs[sel[s]];
        cx += nx[s]; cy += ny[s]; cz += nz[s];
    }
    cx *= (1.0f / KNN); cy *= (1.0f / KNN); cz *= (1.0f / KNN);
    float ss = 0.0f;
    #pragma unroll
    for (int s = 0; s < KNN; s++) {
        float dx = nx[s] - cx, dy = ny[s] - cy, dz = nz[s] - cz;
        ss = fmaf(dx, dx, ss);
        ss = fmaf(dy, dy, ss);
        ss = fmaf(dz, dz, ss);
    }
    out[b * NPTS + qi] = ss * (1.0f / (KNN - 1));
}

// Per-batch normalization: out[b,n] = trace[b,n] / (sum_n trace[b,n] + 1e-8)
__global__ __launch_bounds__(512)
void norm_kernel(float* __restrict__ out)
{
    __shared__ float red[512];
    const int b = blockIdx.x;
    const int tid = threadIdx.x;
    float* o = out + b * NPTS;

    float v[8];
    float s = 0.0f;
    #pragma unroll
    for (int r = 0; r < 8; r++) { v[r] = o[tid + r * 512]; s += v[r]; }
    red[tid] = s;
    __syncthreads();
    #pragma unroll
    for (int off = 256; off > 0; off >>= 1) {
        if (tid < off) red[tid] += red[tid + off];
        __syncthreads();
    }
    float inv = 1.0f / (red[0] + 1e-8f);
    #pragma unroll
    for (int r = 0; r < 8; r++) o[tid + r * 512] = v[r] * inv;
}

extern "C" void kernel_launch(void* const* d_in, const int* in_sizes, int n_in,
                              void* d_out, int out_size)
{
    const float* pcd = (const float*)d_in[0];   // [8, 4096, 3] fp32
    float* out = (float*)d_out;                 // [8, 4096] fp32
    (void)in_sizes; (void)n_in; (void)out_size; // k fixed at 5

    const size_t smem_bytes = (size_t)4 * NPTS * sizeof(float);  // 64 KB
    cudaFuncSetAttribute(knn_curv_kernel,
                         cudaFuncAttributeMaxDynamicSharedMemorySize,
                         (int)smem_bytes);

    dim3 grid(NPTS / QPB, 8);   // (16, 8) = 128 blocks, 1 thread/query
    knn_curv_kernel<<<grid, QPB, smem_bytes>>>(pcd, out);
    norm_kernel<<<8, 512>>>(out);
}

// round 10
// speedup vs baseline: 1.3171x; 1.2748x over previous
#include <cuda_runtime.h>
#include <math_constants.h>

// MC3DAD curvature: per-point kNN (k=5) covariance trace, batch-normalized.
// pcd: [8, 4096, 3] fp32.  out: [8, 4096] fp32.
// 4 threads per query: each scans a disjoint 1024-candidate quarter, then a
// 4-way merge of the sorted top-5 lists (tie-break = lowest index, preserved
// because quarters are ascending disjoint ranges and merge prefers lower list).

#define NPTS    4096
#define THREADS 512
#define QPB     128      // queries per block (THREADS/4)
#define SPLIT   4        // threads per query
#define SEG     (NPTS / SPLIT)   // 1024 candidates per thread
#define KNN     5

typedef unsigned long long ull;

// ---- packed f32x2 helpers (Blackwell sm_100+) ----
__device__ __forceinline__ ull pack2(float lo, float hi) {
    ull r; asm("mov.b64 %0, {%1, %2};" : "=l"(r) : "f"(lo), "f"(hi)); return r;
}
__device__ __forceinline__ ull mul2(ull a, ull b) {
    ull d; asm("mul.rn.f32x2 %0, %1, %2;" : "=l"(d) : "l"(a), "l"(b)); return d;
}
__device__ __forceinline__ ull fma2(ull a, ull b, ull c) {
    ull d; asm("fma.rn.f32x2 %0, %1, %2, %3;" : "=l"(d) : "l"(a), "l"(b), "l"(c)); return d;
}
__device__ __forceinline__ void fma2u(float& lo, float& hi, ull a, ull b, ull c) {
    asm("{\n\t.reg .b64 t;\n\tfma.rn.f32x2 t, %2, %3, %4;\n\tmov.b64 {%0, %1}, t;\n\t}"
        : "=f"(lo), "=f"(hi) : "l"(a), "l"(b), "l"(c));
}

// Sorted-ascending top-5 insert; strict '<' preserves stable lowest-index
// tie-break (scan order is ascending j). Values are in the shifted domain
// d2 - sqq; the sqrt(max(d2,0)) clamp becomes max(v, -sqq).
__device__ __forceinline__ void ins5(float v, int j, float msqq,
    float& bd0, float& bd1, float& bd2, float& bd3, float& bd4,
    int& bi0, int& bi1, int& bi2, int& bi3, int& bi4)
{
    v = fmaxf(v, msqq);
    if (v < bd4) {
        bool p3 = v < bd3;
        bool p2 = v < bd2;
        bool p1 = v < bd1;
        bool p0 = v < bd0;
        bd4 = p3 ? bd3 : v;               bi4 = p3 ? bi3 : j;
        bd3 = p3 ? (p2 ? bd2 : v) : bd3;  bi3 = p3 ? (p2 ? bi2 : j) : bi3;
        bd2 = p2 ? (p1 ? bd1 : v) : bd2;  bi2 = p2 ? (p1 ? bi1 : j) : bi2;
        bd1 = p1 ? (p0 ? bd0 : v) : bd1;  bi1 = p1 ? (p0 ? bi0 : j) : bi1;
        bd0 = p0 ? v : bd0;               bi0 = p0 ? j : bi0;
    }
}

__global__ __launch_bounds__(THREADS, 2)
void knn_curv_kernel(const float* __restrict__ pcd, float* __restrict__ out)
{
    extern __shared__ float smem[];
    float* xs = smem;                 // [4096]
    float* ys = smem + NPTS;          // [4096]
    float* zs = smem + 2 * NPTS;      // [4096]
    float* sq = smem + 3 * NPTS;      // [4096]
    float* md = smem + 4 * NPTS;              // [THREADS*KNN]
    int*   mi = (int*)(md + THREADS * KNN);   // [THREADS*KNN]

    const int b   = blockIdx.y;
    const int tid = threadIdx.x;
    const float* g = pcd + (size_t)b * NPTS * 3;

    // Stage batch point cloud into SMEM as SoA.
    for (int i = tid; i < NPTS * 3; i += THREADS) {
        float v = g[i];
        int p = i / 3, c = i - 3 * p;
        float* dst = (c == 0) ? xs : (c == 1) ? ys : zs;
        dst[p] = v;
    }
    __syncthreads();
    for (int p = tid; p < NPTS; p += THREADS) {
        float x = xs[p], y = ys[p], z = zs[p];
        sq[p] = fmaf(x, x, fmaf(y, y, z * z));
    }
    __syncthreads();

    // Warp-uniform quarter: all 32 lanes of a warp share one quarter.
    const int ql  = tid & (QPB - 1);          // query-local index
    const int qtr = tid >> 7;                 // 0..3 candidate quarter
    const int qi  = blockIdx.x * QPB + ql;    // query index within batch

    const float qx = xs[qi], qy = ys[qi], qz = zs[qi];
    const float sqq = sq[qi];
    const float msqq = -sqq;

    const ull qx2 = pack2(qx, qx);
    const ull qy2 = pack2(qy, qy);
    const ull qz2 = pack2(qz, qz);
    const ull n2  = pack2(-2.0f, -2.0f);

    float bd0 = CUDART_INF_F, bd1 = CUDART_INF_F, bd2 = CUDART_INF_F,
          bd3 = CUDART_INF_F, bd4 = CUDART_INF_F;
    int bi0 = 0, bi1 = 0, bi2 = 0, bi3 = 0, bi4 = 0;

    const int j0 = qtr * SEG;
    #pragma unroll 2
    for (int j = j0; j < j0 + SEG; j += 8) {
        longlong2 X0 = *(const longlong2*)(xs + j);
        longlong2 X1 = *(const longlong2*)(xs + j + 4);
        longlong2 Y0 = *(const longlong2*)(ys + j);
        longlong2 Y1 = *(const longlong2*)(ys + j + 4);
        longlong2 Z0 = *(const longlong2*)(zs + j);
        longlong2 Z1 = *(const longlong2*)(zs + j + 4);
        longlong2 S0 = *(const longlong2*)(sq + j);
        longlong2 S1 = *(const longlong2*)(sq + j + 4);

        float v0, v1, v2, v3, v4, v5, v6, v7;
        { ull t = mul2(qz2, (ull)Z0.x); t = fma2(qy2, (ull)Y0.x, t);
          t = fma2(qx2, (ull)X0.x, t);  fma2u(v0, v1, n2, t, (ull)S0.x); }
        { ull t = mul2(qz2, (ull)Z0.y); t = fma2(qy2, (ull)Y0.y, t);
          t = fma2(qx2, (ull)X0.y, t);  fma2u(v2, v3, n2, t, (ull)S0.y); }
        { ull t = mul2(qz2, (ull)Z1.x); t = fma2(qy2, (ull)Y1.x, t);
          t = fma2(qx2, (ull)X1.x, t);  fma2u(v4, v5, n2, t, (ull)S1.x); }
        { ull t = mul2(qz2, (ull)Z1.y); t = fma2(qy2, (ull)Y1.y, t);
          t = fma2(qx2, (ull)X1.y, t);  fma2u(v6, v7, n2, t, (ull)S1.y); }

        float m = fminf(fminf(fminf(v0, v1), fminf(v2, v3)),
                        fminf(fminf(v4, v5), fminf(v6, v7)));
        if (m < bd4) {
            ins5(v0, j + 0, msqq, bd0, bd1, bd2, bd3, bd4, bi0, bi1, bi2, bi3, bi4);
            ins5(v1, j + 1, msqq, bd0, bd1, bd2, bd3, bd4, bi0, bi1, bi2, bi3, bi4);
            ins5(v2, j + 2, msqq, bd0, bd1, bd2, bd3, bd4, bi0, bi1, bi2, bi3, bi4);
            ins5(v3, j + 3, msqq, bd0, bd1, bd2, bd3, bd4, bi0, bi1, bi2, bi3, bi4);
            ins5(v4, j + 4, msqq, bd0, bd1, bd2, bd3, bd4, bi0, bi1, bi2, bi3, bi4);
            ins5(v5, j + 5, msqq, bd0, bd1, bd2, bd3, bd4, bi0, bi1, bi2, bi3, bi4);
            ins5(v6, j + 6, msqq, bd0, bd1, bd2, bd3, bd4, bi0, bi1, bi2, bi3, bi4);
            ins5(v7, j + 7, msqq, bd0, bd1, bd2, bd3, bd4, bi0, bi1, bi2, bi3, bi4);
        }
    }

    // Publish per-thread sorted top-5 lists. Layout: list for (ql, qtr)
    // at base (qtr*QPB + ql)*KNN == tid*KNN.
    {
        int base = tid * KNN;
        md[base + 0] = bd0; mi[base + 0] = bi0;
        md[base + 1] = bd1; mi[base + 1] = bi1;
        md[base + 2] = bd2; mi[base + 2] = bi2;
        md[base + 3] = bd3; mi[base + 3] = bi3;
        md[base + 4] = bd4; mi[base + 4] = bi4;
    }
    __syncthreads();

    if (qtr == 0) {
        // 4-way merge of sorted lists; on ties pick the lowest quarter
        // (= lowest global index, since quarters cover ascending ranges).
        int base0 = ql * KNN;
        int pos[SPLIT] = {0, 0, 0, 0};
        int sel[KNN];
        #pragma unroll
        for (int s = 0; s < KNN; s++) {
            float best = md[base0 + pos[0]];
            int   bl   = 0;
            #pragma unroll
            for (int l = 1; l < SPLIT; l++) {
                float d = md[base0 + l * QPB * KNN + pos[l]];
                if (d < best) { best = d; bl = l; }
            }
            sel[s] = mi[base0 + bl * QPB * KNN + pos[bl]];
            pos[bl]++;
        }

        // Gather neighbors, centroid, covariance trace (k=5, /(k-1)).
        float nx[KNN], ny[KNN], nz[KNN];
        float cx = 0.0f, cy = 0.0f, cz = 0.0f;
        #pragma unroll
        for (int s = 0; s < KNN; s++) {
            nx[s] = xs[sel[s]]; ny[s] = ys[sel[s]]; nz[s] = zs[sel[s]];
            cx += nx[s]; cy += ny[s]; cz += nz[s];
        }
        cx *= (1.0f / KNN); cy *= (1.0f / KNN); cz *= (1.0f / KNN);
        float ss = 0.0f;
        #pragma unroll
        for (int s = 0; s < KNN; s++) {
            float dx = nx[s] - cx, dy = ny[s] - cy, dz = nz[s] - cz;
            ss = fmaf(dx, dx, ss);
            ss = fmaf(dy, dy, ss);
            ss = fmaf(dz, dz, ss);
        }
        out[b * NPTS + qi] = ss * (1.0f / (KNN - 1));
    }
}

// Per-batch normalization: out[b,n] = trace[b,n] / (sum_n trace[b,n] + 1e-8)
__global__ __launch_bounds__(512)
void norm_kernel(float* __restrict__ out)
{
    __shared__ float red[512];
    const int b = blockIdx.x;
    const int tid = threadIdx.x;
    float* o = out + b * NPTS;

    float v[8];
    float s = 0.0f;
    #pragma unroll
    for (int r = 0; r < 8; r++) { v[r] = o[tid + r * 512]; s += v[r]; }
    red[tid] = s;
    __syncthreads();
    #pragma unroll
    for (int off = 256; off > 0; off >>= 1) {
        if (tid < off) red[tid] += red[tid + off];
        __syncthreads();
    }
    float inv = 1.0f / (red[0] + 1e-8f);
    #pragma unroll
    for (int r = 0; r < 8; r++) o[tid + r * 512] = v[r] * inv;
}

extern "C" void kernel_launch(void* const* d_in, const int* in_sizes, int n_in,
                              void* d_out, int out_size)
{
    const float* pcd = (const float*)d_in[0];   // [8, 4096, 3] fp32
    float* out = (float*)d_out;                 // [8, 4096] fp32
    (void)in_sizes; (void)n_in; (void)out_size; // k fixed at 5

    const size_t smem_bytes = (size_t)4 * NPTS * sizeof(float)        // xs,ys,zs,sq
                            + (size_t)THREADS * KNN * sizeof(float)   // md
                            + (size_t)THREADS * KNN * sizeof(int);    // mi
    cudaFuncSetAttribute(knn_curv_kernel,
                         cudaFuncAttributeMaxDynamicSharedMemorySize,
                         (int)smem_bytes);

    dim3 grid(NPTS / QPB, 8);   // (32, 8) = 256 blocks, 4 threads/query
    knn_curv_kernel<<<grid, THREADS, smem_bytes>>>(pcd, out);
    norm_kernel<<<8, 512>>>(out);
}